// round 3
// baseline (speedup 1.0000x reference)
#include <cuda_runtime.h>

#define BB   64
#define SS   4096
#define HH   256
#define FF   512      // 2*H
#define OUTD 24
#define NCHUNK 16     // s-chunks for context partials

// ---------------- scratch (static device globals; no allocs) ----------------
__device__ __align__(16) float g_qWh[BB*HH];      // hidden_q @ W_h + attn_b
__device__ __align__(16) float g_embT[BB*HH];     // gathered emb_temp
__device__ __align__(16) float g_scores[BB*SS];   // scores -> attn (in place)
__device__ __align__(16) float g_part[NCHUNK*BB*FF]; // context partial sums

// ---------------- helpers ----------------
__device__ __forceinline__ void cp_async16(void* sm, const void* g) {
    unsigned s = (unsigned)__cvta_generic_to_shared(sm);
    asm volatile("cp.async.cg.shared.global [%0], [%1], 16;" :: "r"(s), "l"(g));
}
#define CP_COMMIT() asm volatile("cp.async.commit_group;")
#define CP_WAIT0()  asm volatile("cp.async.wait_group 0;")

__device__ __forceinline__ unsigned long long dup_f32x2(float a) {
    unsigned long long r;
    unsigned ai = __float_as_uint(a);
    asm("mov.b64 %0, {%1, %1};" : "=l"(r) : "r"(ai));
    return r;
}
__device__ __forceinline__ void fma_f32x2(unsigned long long& acc,
                                          unsigned long long a,
                                          unsigned long long b) {
    asm("fma.rn.f32x2 %0, %1, %2, %0;" : "+l"(acc) : "l"(a), "l"(b));
}
__device__ __forceinline__ float2 unpack_f32x2(unsigned long long p) {
    unsigned lo, hi;
    asm("mov.b64 {%0, %1}, %2;" : "=r"(lo), "=r"(hi) : "l"(p));
    return make_float2(__uint_as_float(lo), __uint_as_float(hi));
}
__device__ __forceinline__ float sigmoidf_(float x) { return 1.0f / (1.0f + expf(-x)); }

// ---------------- kernel 1: gathers + qWh = emb_ctxt[idx] @ W_h + attn_b ----
__global__ void setup_kernel(const int* __restrict__ fc, const int* __restrict__ ft,
                             const float* __restrict__ emb_c, const float* __restrict__ emb_t,
                             const float* __restrict__ attn_W, const float* __restrict__ attn_b)
{
    __shared__ float q[HH];
    int b = blockIdx.x, tid = threadIdx.x;
    int ci = fc[b], ti = ft[b];
    q[tid] = emb_c[ci*HH + tid];
    g_embT[b*HH + tid] = emb_t[ti*HH + tid];
    __syncthreads();
    float acc = attn_b[tid];
#pragma unroll 8
    for (int k = 0; k < HH; k++) acc += q[k] * attn_W[k*HH + tid];
    g_qWh[b*HH + tid] = acc;
}

// ---------------- kernel 2: fused scores GEMM ----------------
// scores[b][s] = v . tanh( qWh[b] + E[b,s,:] @ W_e )
// CTA tile: 64 s-rows x 256 H-cols x K=512 (BK=16, double buffered).
// 256 threads = 16(tx: n) x 16(ty: m); thread tile 4m x 16n (8 f32x2 pairs).
__global__ void __launch_bounds__(256, 2)
scores_kernel(const float* __restrict__ E, const float* __restrict__ attn_W,
              const float* __restrict__ v)
{
    __shared__ float As[2][16][65];    // [k][m] (+pad) transposed E tile
    __shared__ float Bs[2][16][256];   // [k][n] W_e tile

    const int b  = blockIdx.y;
    const int s0 = blockIdx.x * 64;
    const int tid = threadIdx.x;
    const int tx = tid & 15, ty = tid >> 4;

    const float* We = attn_W + HH*HH;  // W_e = attn_W rows [256, 768)

    // A load indices: each thread one float4 per tile
    const int am = tid >> 2, aq = tid & 3;
    const float* Arow = E + (long)(b*SS + s0 + am) * FF;

    unsigned long long acc[4][8];
#pragma unroll
    for (int j = 0; j < 4; j++)
#pragma unroll
        for (int jj = 0; jj < 8; jj++) acc[j][jj] = 0ULL;

    // ---- prologue: tile 0 ----
    {
#pragma unroll
        for (int r = 0; r < 4; r++) {
            int idx = tid + 256*r;
            int kk = idx >> 6, nq = idx & 63;
            cp_async16(&Bs[0][kk][nq*4], We + (0 + kk)*HH + nq*4);
        }
        CP_COMMIT();
        float4 a4 = *(const float4*)(Arow + 0 + aq*4);
        As[0][aq*4+0][am] = a4.x; As[0][aq*4+1][am] = a4.y;
        As[0][aq*4+2][am] = a4.z; As[0][aq*4+3][am] = a4.w;
        CP_WAIT0();
        __syncthreads();
    }

    // ---- main loop over 32 K-tiles ----
    for (int t = 0; t < 32; t++) {
        const int cur = t & 1;
        float4 a4;
        if (t < 31) {
            const int k0 = (t+1)*16;
#pragma unroll
            for (int r = 0; r < 4; r++) {
                int idx = tid + 256*r;
                int kk = idx >> 6, nq = idx & 63;
                cp_async16(&Bs[cur^1][kk][nq*4], We + (k0 + kk)*HH + nq*4);
            }
            CP_COMMIT();
            a4 = *(const float4*)(Arow + k0 + aq*4);
        }

#pragma unroll
        for (int kk = 0; kk < 16; kk++) {
            const unsigned long long* Brow = (const unsigned long long*)&Bs[cur][kk][0];
            unsigned long long bfrag[8];
#pragma unroll
            for (int jj = 0; jj < 8; jj++) bfrag[jj] = Brow[tx + jj*16];
            unsigned long long afrag[4];
#pragma unroll
            for (int j = 0; j < 4; j++) afrag[j] = dup_f32x2(As[cur][kk][ty + j*16]);
#pragma unroll
            for (int j = 0; j < 4; j++)
#pragma unroll
                for (int jj = 0; jj < 8; jj++) fma_f32x2(acc[j][jj], afrag[j], bfrag[jj]);
        }

        if (t < 31) {
            As[cur^1][aq*4+0][am] = a4.x; As[cur^1][aq*4+1][am] = a4.y;
            As[cur^1][aq*4+2][am] = a4.z; As[cur^1][aq*4+3][am] = a4.w;
            CP_WAIT0();
        }
        __syncthreads();
    }

    // ---- epilogue: +qWh, tanh, dot v, half-warp reduce over tx ----
    float2 vv[8], qw[8];
#pragma unroll
    for (int jj = 0; jj < 8; jj++) {
        const int n0 = tx*2 + jj*32;
        vv[jj] = *(const float2*)(v + n0);
        qw[jj] = *(const float2*)(&g_qWh[b*HH + n0]);
    }
    float sc[4];
#pragma unroll
    for (int j = 0; j < 4; j++) {
        float p = 0.0f;
#pragma unroll
        for (int jj = 0; jj < 8; jj++) {
            float2 q2 = unpack_f32x2(acc[j][jj]);
            p += vv[jj].x * tanhf(q2.x + qw[jj].x);
            p += vv[jj].y * tanhf(q2.y + qw[jj].y);
        }
#pragma unroll
        for (int o = 8; o; o >>= 1) p += __shfl_xor_sync(0xffffffffu, p, o);
        sc[j] = p;
    }
    if (tx == 0) {
#pragma unroll
        for (int j = 0; j < 4; j++) g_scores[b*SS + s0 + ty + j*16] = sc[j];
    }
}

// ---------------- kernel 3: softmax over S per batch (in place) -------------
__global__ void softmax_kernel()
{
    __shared__ float red[32];
    const int b = blockIdx.x, tid = threadIdx.x;
    float* row = g_scores + b*SS;
    float4 xv = *(float4*)(row + tid*4);
    const unsigned lane = tid & 31, w = tid >> 5;

    float m = fmaxf(fmaxf(xv.x, xv.y), fmaxf(xv.z, xv.w));
#pragma unroll
    for (int o = 16; o; o >>= 1) m = fmaxf(m, __shfl_xor_sync(0xffffffffu, m, o));
    if (!lane) red[w] = m;
    __syncthreads();
    if (tid < 32) {
        float t = red[tid];
#pragma unroll
        for (int o = 16; o; o >>= 1) t = fmaxf(t, __shfl_xor_sync(0xffffffffu, t, o));
        if (!tid) red[0] = t;
    }
    __syncthreads();
    const float mm = red[0];
    __syncthreads();

    float4 ev = make_float4(expf(xv.x - mm), expf(xv.y - mm),
                            expf(xv.z - mm), expf(xv.w - mm));
    float s = ev.x + ev.y + ev.z + ev.w;
#pragma unroll
    for (int o = 16; o; o >>= 1) s += __shfl_xor_sync(0xffffffffu, s, o);
    if (!lane) red[w] = s;
    __syncthreads();
    if (tid < 32) {
        float t = red[tid];
#pragma unroll
        for (int o = 16; o; o >>= 1) t += __shfl_xor_sync(0xffffffffu, t, o);
        if (!tid) red[0] = t;
    }
    __syncthreads();
    const float inv = 1.0f / red[0];
    ev.x *= inv; ev.y *= inv; ev.z *= inv; ev.w *= inv;
    *(float4*)(row + tid*4) = ev;
}

// ---------------- kernel 4: context partials: part[c][b][f] ----------------
__global__ void ctx_kernel(const float* __restrict__ E)
{
    __shared__ float sa[SS / NCHUNK];
    const int c = blockIdx.x, b = blockIdx.y, tid = threadIdx.x; // 128 threads
    const int s0 = c * (SS / NCHUNK);
    sa[tid]       = g_scores[b*SS + s0 + tid];
    sa[tid + 128] = g_scores[b*SS + s0 + tid + 128];
    __syncthreads();

    float4 acc = make_float4(0.f, 0.f, 0.f, 0.f);
    const float* base = E + (long)(b*SS + s0) * FF + tid*4;
#pragma unroll 8
    for (int s = 0; s < SS / NCHUNK; s++) {
        const float a = sa[s];
        const float4 e = *(const float4*)(base + (long)s * FF);
        acc.x += a*e.x; acc.y += a*e.y; acc.z += a*e.z; acc.w += a*e.w;
    }
    *(float4*)(&g_part[(long)(c*BB + b)*FF + tid*4]) = acc;
}

// ---------------- kernel 5: reduce + GRU + output projection ----------------
__global__ void gru_kernel(const float* __restrict__ w_ih, const float* __restrict__ b_ih,
                           const float* __restrict__ b_hh, const float* __restrict__ out_W,
                           const float* __restrict__ out_b, float* __restrict__ out,
                           int out_size)
{
    __shared__ float x[3*HH];
    __shared__ float g[3*HH];
    __shared__ float h[HH];
    const int b = blockIdx.x, tid = threadIdx.x; // 256 threads

    // context reduce over NCHUNK partials -> x[256..767]
#pragma unroll
    for (int r = 0; r < 2; r++) {
        const int f = tid + r*256;
        float acc = 0.0f;
#pragma unroll
        for (int c = 0; c < NCHUNK; c++) acc += g_part[(long)(c*BB + b)*FF + f];
        x[HH + f] = acc;
    }
    x[tid] = g_embT[b*HH + tid];
    __syncthreads();

    // gi = x @ w_ih + b_ih   (768x768)
#pragma unroll
    for (int r = 0; r < 3; r++) {
        const int jj = tid + r*256;
        float acc = b_ih[jj];
#pragma unroll 8
        for (int k = 0; k < 3*HH; k++) acc += x[k] * w_ih[k*(3*HH) + jj];
        g[jj] = acc;
    }
    __syncthreads();

    // gates (h0 = 0  =>  gh = b_hh exactly)
    {
        const int j = tid;
        const float rg = sigmoidf_(g[j]        + b_hh[j]);
        const float zg = sigmoidf_(g[HH + j]   + b_hh[HH + j]);
        const float ng = tanhf   (g[2*HH + j]  + rg * b_hh[2*HH + j]);
        const float hv = (1.0f - zg) * ng;
        h[j] = hv;
        const int ho = BB*OUTD + b*HH + j;
        if (ho < out_size) out[ho] = hv;
    }
    __syncthreads();

    // output = h @ out_W + out_b
    if (tid < OUTD) {
        float acc = out_b[tid];
#pragma unroll 8
        for (int k = 0; k < HH; k++) acc += h[k] * out_W[k*OUTD + tid];
        out[b*OUTD + tid] = acc;
    }
}

// ---------------- launch ----------------
extern "C" void kernel_launch(void* const* d_in, const int* in_sizes, int n_in,
                              void* d_out, int out_size)
{
    const int*   fc     = (const int*)  d_in[0];   // fut_ctxt (B,1)
    const int*   ft     = (const int*)  d_in[1];   // fut_temp (B,1)
    const float* E      = (const float*)d_in[2];   // encoder_outputs (B,S,2H)
    const float* emb_c  = (const float*)d_in[3];   // emb_ctxt (1000,H)
    const float* emb_t  = (const float*)d_in[4];   // emb_temp (1000,H)
    const float* attn_W = (const float*)d_in[5];   // (3H,H)
    const float* attn_b = (const float*)d_in[6];   // (H,)
    const float* v      = (const float*)d_in[7];   // (H,)
    const float* w_ih   = (const float*)d_in[8];   // (3H,3H)
    // d_in[9] = w_hh: unused since h0 == 0 (gh = b_hh exactly)
    const float* b_ih   = (const float*)d_in[10];  // (3H,)
    const float* b_hh   = (const float*)d_in[11];  // (3H,)
    const float* out_W  = (const float*)d_in[12];  // (H,OUT)
    const float* out_b  = (const float*)d_in[13];  // (OUT,)
    float* out = (float*)d_out;

    setup_kernel<<<BB, HH>>>(fc, ft, emb_c, emb_t, attn_W, attn_b);
    scores_kernel<<<dim3(SS/64, BB), 256>>>(E, attn_W, v);
    softmax_kernel<<<BB, 1024>>>();
    ctx_kernel<<<dim3(NCHUNK, BB), 128>>>(E);
    gru_kernel<<<BB, 256>>>(w_ih, b_ih, b_hh, out_W, out_b, out, out_size);
}